// round 14
// baseline (speedup 1.0000x reference)
#include <cuda_runtime.h>

// ---------------------------------------------------------------------------
// SSIM (16,3,512,512) fp32, 11x11 Gaussian (sigma=1.5), zero pad, global mean.
// R14: 2 columns/thread AND 16 warps/SM: NT=256, __launch_bounds__(256,2),
// grid = 6 bands x 48 planes = 288 CTAs = 2 CTAs/SM. Streamed h-conv
// (6x ld.shared.v2.u64 chunks, rolling 2-chunk register window) keeps
// regs <= 128. Warp-private halo rows of (S,D) float2 pairs (Hadamard
// transform in SMEM, pipelined one row ahead). cp.async depth-3 over 8
// rotating buffers. Static mod-11 f32x2 vertical rings per column.
// ---------------------------------------------------------------------------

#define IMW     512
#define IMH     512
#define NT      256                 // one thread per 2 columns
#define TH      86                  // output rows per band (6 bands cover 512)
#define NBANDS  6
#define NPLANES 48                  // 16 * 3
#define NBLOCKS (NPLANES * NBANDS)  // 288 CTAs -> 2 per SM, single wave
#define SSIM_C1 0.0001f
#define SSIM_C2 0.0009f

typedef unsigned long long ull;

__device__ float        g_partials[NBLOCKS];
__device__ unsigned int g_count;    // zero-init; reset by last block each run

#define CPA4_O(daddr, sptr, D, S) \
    asm volatile("cp.async.ca.shared.global [%0+" #D "], [%1+" #S "], 4;" \
                 :: "r"(daddr), "l"(sptr))
#define CPA_COMMIT() asm volatile("cp.async.commit_group;" ::: "memory")
#define CPA_WAIT2()  asm volatile("cp.async.wait_group 2;"  ::: "memory")
#define CPA_WAIT1()  asm volatile("cp.async.wait_group 1;"  ::: "memory")

#define LDS128(d0, d1, a) \
    asm volatile("ld.shared.v2.u64 {%0,%1}, [%2];" \
                 : "=l"(d0), "=l"(d1) : "r"(a))
#define MUL2(d, a, b) \
    asm("mul.rn.f32x2 %0, %1, %2;" : "=l"(d) : "l"(a), "l"(b))
#define FMA2ACC(acc, a, b) \
    asm("fma.rn.f32x2 %0, %1, %2, %0;" : "+l"(acc) : "l"(a), "l"(b))
#define UNPACK2(lo, hi, s) \
    asm("mov.b64 {%0, %1}, %2;" : "=f"(lo), "=f"(hi) : "l"(s))

// Transform this lane's 2 main slots (16B at A) from (x,y) to (x+y, x-y).
#define TRANSMAIN(A) do {                                                     \
    float x0_, y0_, x1_, y1_;                                                 \
    asm volatile("ld.shared.v4.f32 {%0,%1,%2,%3}, [%4];"                      \
                 : "=f"(x0_), "=f"(y0_), "=f"(x1_), "=f"(y1_) : "r"(A));      \
    const float s0_ = x0_ + y0_, d0_ = x0_ - y0_;                             \
    const float s1_ = x1_ + y1_, d1_ = x1_ - y1_;                             \
    asm volatile("st.shared.v4.f32 [%0], {%1,%2,%3,%4};"                      \
                 :: "r"(A), "f"(s0_), "f"(d0_), "f"(s1_), "f"(d1_));          \
} while (0)
#define TRANSTAIL(A) do {                                                     \
    float xt_, yt_;                                                           \
    asm volatile("ld.shared.v2.f32 {%0,%1}, [%2];"                            \
                 : "=f"(xt_), "=f"(yt_) : "r"(A));                            \
    const float st_ = xt_ + yt_, dt_ = xt_ - yt_;                             \
    asm volatile("st.shared.v2.f32 [%0], {%1,%2};"                            \
                 :: "r"(A), "f"(st_), "f"(dt_));                              \
} while (0)
#define TRANSROW(rn) do {                                                     \
    const unsigned ta_ = sbu + (unsigned)((rn) & 7) * BSTRIDE;                \
    TRANSMAIN(ta_);                                                           \
    if (tailst) TRANSTAIL(ta_ + tailoffB);                                    \
} while (0)

// SSIM extraction from packed ring slots (one column).
#define EXTRACT(PQ, SD) do {                                                  \
    float p_, q_, sv_, dv_;                                                   \
    UNPACK2(p_, q_, PQ);                                                      \
    UNPACK2(sv_, dv_, SD);                                                    \
    const float a2_ = p_ * p_;                                                \
    const float b2_ = q_ * q_;                                                \
    const float U_  = a2_ + b2_;                                              \
    const float V_  = a2_ - b2_;                                              \
    const float M_  = sv_ + dv_;                                              \
    const float N2_ = sv_ - dv_;                                              \
    const float t1_ = 0.5f * V_ + SSIM_C1;                                    \
    const float t2_ = 0.5f * (N2_ - V_) + SSIM_C2;                            \
    const float t3_ = 0.5f * U_ + SSIM_C1;                                    \
    const float t4_ = 0.5f * (M_ - U_) + SSIM_C2;                             \
    ssum += __fdividef(t1_ * t2_, t3_ * t4_);                                 \
} while (0)

// Streamed h-conv (both columns) + rings + extraction.
// P compile-time == ir_ mod 11. Window slots j=0..11 at rb+8j:
//   col A taps j=0..10 weight W[j]; col B taps j=1..11 weight W[j-1].
#define ROWMATH(P, ir_) do {                                                  \
    const unsigned rb_ = sbu + (unsigned)((ir_) & 7) * BSTRIDE;               \
    ull cx0, cx1, cy0, cy1, s0_, s1_;                                         \
    ull hlA, hsA, hlB, hsB;                                                   \
    LDS128(cx0, cx1, rb_);                                                    \
    LDS128(cy0, cy1, rb_ + 16u);                                              \
    /* chunk0: j=0,1 */                                                       \
    MUL2(s0_, cx0, cx0); MUL2(s1_, cx1, cx1);                                 \
    MUL2(hlA, cx0, W2[0]);       MUL2(hsA, s0_, W2[0]);                       \
    FMA2ACC(hlA, cx1, W2[1]);    FMA2ACC(hsA, s1_, W2[1]);                    \
    MUL2(hlB, cx1, W2[0]);       MUL2(hsB, s1_, W2[0]);                       \
    LDS128(cx0, cx1, rb_ + 32u);                                              \
    /* chunk1: j=2,3 */                                                       \
    MUL2(s0_, cy0, cy0); MUL2(s1_, cy1, cy1);                                 \
    FMA2ACC(hlA, cy0, W2[2]);    FMA2ACC(hsA, s0_, W2[2]);                    \
    FMA2ACC(hlA, cy1, W2[3]);    FMA2ACC(hsA, s1_, W2[3]);                    \
    FMA2ACC(hlB, cy0, W2[1]);    FMA2ACC(hsB, s0_, W2[1]);                    \
    FMA2ACC(hlB, cy1, W2[2]);    FMA2ACC(hsB, s1_, W2[2]);                    \
    LDS128(cy0, cy1, rb_ + 48u);                                              \
    /* chunk2: j=4,5 */                                                       \
    MUL2(s0_, cx0, cx0); MUL2(s1_, cx1, cx1);                                 \
    FMA2ACC(hlA, cx0, W2[4]);    FMA2ACC(hsA, s0_, W2[4]);                    \
    FMA2ACC(hlA, cx1, W2[5]);    FMA2ACC(hsA, s1_, W2[5]);                    \
    FMA2ACC(hlB, cx0, W2[3]);    FMA2ACC(hsB, s0_, W2[3]);                    \
    FMA2ACC(hlB, cx1, W2[4]);    FMA2ACC(hsB, s1_, W2[4]);                    \
    LDS128(cx0, cx1, rb_ + 64u);                                              \
    /* chunk3: j=6,7 */                                                       \
    MUL2(s0_, cy0, cy0); MUL2(s1_, cy1, cy1);                                 \
    FMA2ACC(hlA, cy0, W2[6]);    FMA2ACC(hsA, s0_, W2[6]);                    \
    FMA2ACC(hlA, cy1, W2[7]);    FMA2ACC(hsA, s1_, W2[7]);                    \
    FMA2ACC(hlB, cy0, W2[5]);    FMA2ACC(hsB, s0_, W2[5]);                    \
    FMA2ACC(hlB, cy1, W2[6]);    FMA2ACC(hsB, s1_, W2[6]);                    \
    LDS128(cy0, cy1, rb_ + 80u);                                              \
    /* chunk4: j=8,9 */                                                       \
    MUL2(s0_, cx0, cx0); MUL2(s1_, cx1, cx1);                                 \
    FMA2ACC(hlA, cx0, W2[8]);    FMA2ACC(hsA, s0_, W2[8]);                    \
    FMA2ACC(hlA, cx1, W2[9]);    FMA2ACC(hsA, s1_, W2[9]);                    \
    FMA2ACC(hlB, cx0, W2[7]);    FMA2ACC(hsB, s0_, W2[7]);                    \
    FMA2ACC(hlB, cx1, W2[8]);    FMA2ACC(hsB, s1_, W2[8]);                    \
    /* chunk5: j=10,11 (A: j=10 only) */                                      \
    MUL2(s0_, cy0, cy0); MUL2(s1_, cy1, cy1);                                 \
    FMA2ACC(hlA, cy0, W2[10]);   FMA2ACC(hsA, s0_, W2[10]);                   \
    FMA2ACC(hlB, cy0, W2[9]);    FMA2ACC(hsB, s0_, W2[9]);                    \
    FMA2ACC(hlB, cy1, W2[10]);   FMA2ACC(hsB, s1_, W2[10]);                   \
    /* vertical rings (reset folded into MUL2 at tap d==0) */                 \
    _Pragma("unroll")                                                         \
    for (int s = 0; s < 11; ++s) {                                            \
        const int d = ((P) - s + 11) % 11;      /* compile-time */            \
        if (s == (P)) {                                                       \
            MUL2(APQa[s], hlA, W2[0]);  MUL2(ASDa[s], hsA, W2[0]);            \
            MUL2(APQb[s], hlB, W2[0]);  MUL2(ASDb[s], hsB, W2[0]);            \
        } else {                                                              \
            FMA2ACC(APQa[s], hlA, W2[d]);  FMA2ACC(ASDa[s], hsA, W2[d]);      \
            FMA2ACC(APQb[s], hlB, W2[d]);  FMA2ACC(ASDb[s], hsB, W2[d]);      \
        }                                                                     \
    }                                                                         \
    const int e_ = ((P) + 1) % 11;              /* compile-time */            \
    if ((ir_) >= 10) {                                                        \
        EXTRACT(APQa[e_], ASDa[e_]);                                          \
        EXTRACT(APQb[e_], ASDb[e_]);                                          \
    }                                                                         \
} while (0)

// Guard-free phase (rows 0..87: fill ir+3 <= 90 <= nrows-2 for all bands).
#define PHASEF(P, IRV) do {                                                   \
    const int irf_ = (IRV);                                                   \
    FILLF(irf_ + 3);                                                          \
    CPA_COMMIT();                                                             \
    CPA_WAIT2();               /* rows <= irf_+1 complete */                  \
    TRANSROW(irf_ + 1);                                                       \
    __syncwarp();                                                             \
    ROWMATH(P, irf_);                                                         \
} while (0)

// Guarded tail phase (rows 88..nrows-1).
#define PHASET(P, IRV) do {                                                   \
    const int irt_ = (IRV);                                                   \
    if (irt_ < nrows) {                                                       \
        if (irt_ + 3 < nrows) FILLF(irt_ + 3);                                \
        CPA_COMMIT();                                                         \
        CPA_WAIT2();                                                          \
        if (irt_ + 1 < nrows) TRANSROW(irt_ + 1);                             \
        __syncwarp();                                                         \
        ROWMATH(P, irt_);                                                     \
    }                                                                         \
} while (0)

__global__ void __launch_bounds__(NT, 2)
ssim_main(const float* __restrict__ img1, const float* __restrict__ img2,
          float* __restrict__ out)
{
    // Normalized 1D Gaussian, sigma=1.5, 11 taps
    const float W[11] = {
        0.00102838f, 0.00759874f, 0.03600077f, 0.10936069f, 0.21300553f,
        0.26601180f,
        0.21300553f, 0.10936069f, 0.03600077f, 0.00759874f, 0.00102838f
    };
    ull W2[11];
#pragma unroll
    for (int k = 0; k < 11; ++k) {
        const unsigned u = __float_as_uint(W[k]);
        W2[k] = ((ull)u << 32) | (ull)u;
    }

    const int band  = blockIdx.x;           // 0..5
    const int plane = blockIdx.y;           // 0..47
    const int t     = threadIdx.x;          // 0..255
    const int l     = t & 31;               // lane
    const int w     = t >> 5;               // warp (0..7), covers 64 columns
    const int r0    = band * TH;
    const int rows  = (IMH - r0 < TH) ? (IMH - r0) : TH;   // 86.. / 82 last
    const int nrows = rows + 10;            // 96 / 92
    const int pbase = plane * (IMW * IMH);

    // Warp-private 8-deep rotating halo rows.
    // seg[buf][w][j], j in [0,74): pixel pair at image column 64*w - 5 + j.
    __shared__ __align__(16) float2 seg[8][8][76];

    // Static rings (packed), per column: slot s <-> output rows m % 11 == s.
    ull APQa[11], ASDa[11], APQb[11], ASDb[11];
#pragma unroll
    for (int j = 0; j < 11; ++j) {
        APQa[j] = 0ULL; ASDa[j] = 0ULL; APQb[j] = 0ULL; ASDb[j] = 0ULL;
    }

    // Fill mapping: lane fills slots 2l, 2l+1 (cols 64w-5+2l, 64w-4+2l) and,
    // for l<10, tail slot 64+l (col 64w+59+l).
    const int  cA0    = 64 * w + 2 * l - 5;
    const bool ok0    = (cA0 >= 0);
    const bool ok1    = (cA0 >= -1);
    const int  toff   = 64 - l;             // tail col - cA0
    const bool tailst = (l < 10);
    const bool tailok = tailst && (64 * w + 59 + l < IMW);

    const float* bpA1 = img1 + pbase + cA0;
    const float* bpA2 = img2 + pbase + cA0;

    unsigned sbu;
    asm("{ .reg .u64 tt; cvta.to.shared.u64 tt, %1; cvt.u32.u64 %0, tt; }"
        : "=r"(sbu) : "l"(&seg[0][w][2 * l]));
    const unsigned BSTRIDE  = 8u * 76u * 8u;            // 4864 B per buffer
    const unsigned tailoffB = (unsigned)(toff * 8);     // slot 64+l vs slot 2l

    auto FILLF = [&](int rn) {
        const int gr = r0 - 5 + rn;               // global row (0-pad if OOB)
        const unsigned d = sbu + (unsigned)(rn & 7) * BSTRIDE;
        if ((unsigned)gr < (unsigned)IMH) {
            const int off = gr * IMW;
            const float* pA1 = bpA1 + off;
            const float* pA2 = bpA2 + off;
            if (ok0) { CPA4_O(d, pA1, 0, 0);  CPA4_O(d, pA2, 4, 0); }
            if (ok1) { CPA4_O(d, pA1, 8, 4);  CPA4_O(d, pA2, 12, 4); }
            if (tailok) {
                const unsigned dt = d + tailoffB;
                CPA4_O(dt, pA1 + toff, 0, 0);
                CPA4_O(dt, pA2 + toff, 4, 0);
            }
        } else {
            const float z = 0.f;
            asm volatile("st.shared.v4.f32 [%0], {%1,%1,%1,%1};"
                         :: "r"(d), "f"(z));
            if (tailst)
                asm volatile("st.shared.v2.f32 [%0], {%1,%1};"
                             :: "r"(d + tailoffB), "f"(z));
        }
    };

    // Pre-zero slots never written by cp.async (col-invalid); all 8 buffers.
#pragma unroll
    for (int b = 0; b < 8; ++b) {
        const unsigned d = sbu + (unsigned)b * BSTRIDE;
        const float z = 0.f;
        if (!ok0)
            asm volatile("st.shared.v2.f32 [%0], {%1,%1};" :: "r"(d), "f"(z));
        if (!ok1)
            asm volatile("st.shared.v2.f32 [%0+8], {%1,%1};" :: "r"(d), "f"(z));
        if (tailst && !tailok)
            asm volatile("st.shared.v2.f32 [%0], {%1,%1};"
                         :: "r"(d + tailoffB), "f"(z));
    }

    // Prologue: rows 0,1,2 in flight; rows 0,1 complete; row 0 transformed.
    FILLF(0); CPA_COMMIT();
    FILLF(1); CPA_COMMIT();
    FILLF(2); CPA_COMMIT();
    CPA_WAIT1();
    TRANSROW(0);
    __syncwarp();

    float ssum = 0.f;

    // 8 guard-free blocks: rows 0..87.
#pragma unroll 1
    for (int base = 0; base < 88; base += 11) {
#pragma unroll
        for (int q = 0; q < 11; ++q) {
            PHASEF(q, base + q);
        }
    }
    // Guarded tail: rows 88..nrows-1 (88 % 11 == 0 -> P == q).
    {
#pragma unroll
        for (int q = 0; q < 11; ++q) {
            PHASET(q, 88 + q);
        }
    }

    // ---- deterministic block reduction ----
    __syncthreads();
#pragma unroll
    for (int off = 16; off; off >>= 1)
        ssum += __shfl_xor_sync(0xffffffffu, ssum, off);

    __shared__ float wsum[8];
    __shared__ bool  islast;
    if (l == 0) wsum[w] = ssum;
    __syncthreads();
    if (t == 0) {
        float v = 0.f;
#pragma unroll
        for (int i = 0; i < 8; ++i) v += wsum[i];
        g_partials[plane * NBANDS + band] = v;
        __threadfence();
        const unsigned n = atomicAdd(&g_count, 1u);
        islast = (n == (unsigned)(NBLOCKS - 1));
    }
    __syncthreads();

    // ---- last CTA: fixed-order (deterministic) final reduction ----
    if (islast) {
        __threadfence();
        float v = g_partials[t];
        if (t < NBLOCKS - NT) v += g_partials[NT + t];
#pragma unroll
        for (int off = 16; off; off >>= 1)
            v += __shfl_xor_sync(0xffffffffu, v, off);
        if (l == 0) wsum[w] = v;
        __syncthreads();
        if (t == 0) {
            float s = 0.f;
#pragma unroll
            for (int i = 0; i < 8; ++i) s += wsum[i];
            out[0] = s * (1.0f / 12582912.0f);  // / (16*3*512*512)
            g_count = 0u;                        // reset for next graph replay
        }
    }
}

extern "C" void kernel_launch(void* const* d_in, const int* in_sizes, int n_in,
                              void* d_out, int out_size)
{
    const float* img1 = (const float*)d_in[0];
    const float* img2 = (const float*)d_in[1];
    (void)in_sizes; (void)n_in; (void)out_size;

    dim3 grid(NBANDS, NPLANES);
    ssim_main<<<grid, NT>>>(img1, img2, (float*)d_out);
}

// round 15
// speedup vs baseline: 1.1449x; 1.1449x over previous
#include <cuda_runtime.h>

// ---------------------------------------------------------------------------
// SSIM (16,3,512,512) fp32, 11x11 Gaussian (sigma=1.5), zero pad, global mean.
// R15 = R11 skeleton (NT=512, 1 col/thread, 16 warps, warp-private segments,
// in-SMEM Hadamard (S,D), f32x2 h-conv + static mod-11 ring, cp.async depth-3)
// + REGISTER TAP PREFETCH: taps of row ir+1 are LDS'd at the END of phase ir
// (after TRANS(ir+1)), so each phase's math runs on registers with a full
// phase of LDS latency cover. Removes the per-phase LDS->math stall chain.
// ---------------------------------------------------------------------------

#define IMW     512
#define IMH     512
#define NT      512                 // one thread per column
#define TH      171                 // output rows per band (3 bands cover 512)
#define NBANDS  3
#define NPLANES 48                  // 16 * 3
#define NBLOCKS (NPLANES * NBANDS)  // 144 CTAs -> single wave
#define SSIM_C1 0.0001f
#define SSIM_C2 0.0009f

typedef unsigned long long ull;

__device__ float        g_partials[NBLOCKS];
__device__ unsigned int g_count;    // zero-init; reset by last block each run

#define CPA4(daddr, sptr) \
    asm volatile("cp.async.ca.shared.global [%0], [%1], 4;" \
                 :: "r"(daddr), "l"(sptr))
#define CPA4T(daddr, sptr) \
    asm volatile("cp.async.ca.shared.global [%0+256], [%1+128], 4;" \
                 :: "r"(daddr), "l"(sptr))
#define CPA_COMMIT() asm volatile("cp.async.commit_group;" ::: "memory")
#define CPA_WAIT2()  asm volatile("cp.async.wait_group 2;"  ::: "memory")
#define CPA_WAIT1()  asm volatile("cp.async.wait_group 1;"  ::: "memory")

#define LDS64(d, a) \
    asm volatile("ld.shared.b64 %0, [%1];" : "=l"(d) : "r"(a))
#define ADD2(d, a, b) \
    asm("add.rn.f32x2 %0, %1, %2;" : "=l"(d) : "l"(a), "l"(b))
#define MUL2(d, a, b) \
    asm("mul.rn.f32x2 %0, %1, %2;" : "=l"(d) : "l"(a), "l"(b))
#define FMA2ACC(acc, a, b) \
    asm("fma.rn.f32x2 %0, %1, %2, %0;" : "+l"(acc) : "l"(a), "l"(b))
#define UNPACK2(lo, hi, s) \
    asm("mov.b64 {%0, %1}, %2;" : "=f"(lo), "=f"(hi) : "l"(s))

// (x,y) -> (x+y, x-y) in place at shared address A (one 8-byte slot)
#define TRANS(A) do {                                                         \
    float xa_, xb_;                                                           \
    asm volatile("ld.shared.v2.f32 {%0,%1}, [%2];"                            \
                 : "=f"(xa_), "=f"(xb_) : "r"(A));                            \
    const float s_ = xa_ + xb_, d_ = xa_ - xb_;                               \
    asm volatile("st.shared.v2.f32 [%0], {%1,%2};"                            \
                 :: "r"(A), "f"(s_), "f"(d_));                                \
} while (0)
#define TRANSROW(rn) do {                                                     \
    const unsigned ta_ = sbu + (unsigned)((rn) & 7) * BSTRIDE;                \
    TRANS(ta_);                                                               \
    if (tailst) TRANS(ta_ + 256u);                                            \
} while (0)

// Load the 11 taps of row rn (already transformed) into tp[].
#define ROWLOAD(rn) do {                                                      \
    const unsigned rl_ = sbu + (unsigned)((rn) & 7) * BSTRIDE;                \
    _Pragma("unroll")                                                         \
    for (int k = 0; k < 11; ++k) LDS64(tp[k], rl_ + 8u * k);                  \
} while (0)

// h-conv + ring + extraction for row ir_, taps already in tp[].
// P must be a compile-time constant == ir_ mod 11.
#define ROWMATH(P, ir_) do {                                                  \
    ull hpq, hsd, tc;                                                         \
    MUL2(hpq, tp[5], W2[5]);                                                  \
    MUL2(tc,  tp[5], tp[5]);                                                  \
    MUL2(hsd, tc, W2[5]);                                                     \
    _Pragma("unroll")                                                         \
    for (int k = 0; k < 5; ++k) {   /* symmetric pairs (k, 10-k) */           \
        ull ab, sq;                                                           \
        ADD2(ab, tp[k], tp[10 - k]);                                          \
        FMA2ACC(hpq, ab, W2[k]);                                              \
        MUL2(sq, tp[k], tp[k]);                                               \
        FMA2ACC(sq, tp[10 - k], tp[10 - k]);                                  \
        FMA2ACC(hsd, sq, W2[k]);                                              \
    }                                                                         \
    _Pragma("unroll")                                                         \
    for (int s = 0; s < 11; ++s) {                                            \
        const int d = ((P) - s + 11) % 11;      /* compile-time */            \
        if (s == (P)) {     /* tap d==0: new output starts -> overwrite */    \
            MUL2(APQ[s], hpq, W2[0]);                                         \
            MUL2(ASD[s], hsd, W2[0]);                                         \
        } else {                                                              \
            FMA2ACC(APQ[s], hpq, W2[d]);                                      \
            FMA2ACC(ASD[s], hsd, W2[d]);                                      \
        }                                                                     \
    }                                                                         \
    const int e_ = ((P) + 1) % 11;              /* compile-time */            \
    if ((ir_) >= 10) {          /* output row m = ir-10 is real */            \
        float p, q, sv, dv;                                                   \
        UNPACK2(p, q, APQ[e_]);                                               \
        UNPACK2(sv, dv, ASD[e_]);                                             \
        const float a2 = p * p;                                               \
        const float b2 = q * q;                                               \
        const float U  = a2 + b2;                                             \
        const float V  = a2 - b2;                                             \
        const float M  = sv + dv;                                             \
        const float N2 = sv - dv;                                             \
        const float t1 = 0.5f * V + SSIM_C1;                                  \
        const float t2 = 0.5f * (N2 - V) + SSIM_C2;                           \
        const float t3 = 0.5f * U + SSIM_C1;                                  \
        const float t4 = 0.5f * (M - U) + SSIM_C2;                            \
        ssum += __fdividef(t1 * t2, t3 * t4);                                 \
    }                                                                         \
} while (0)

// Guard-free phase (rows 0..175): math on prefetched taps, then refill +
// transform + prefetch next row's taps.
#define PHASEF(P, IRV) do {                                                   \
    const int irf_ = (IRV);                                                   \
    ROWMATH(P, irf_);                                                         \
    FILLF(irf_ + 3);                                                          \
    CPA_COMMIT();                                                             \
    CPA_WAIT2();               /* rows <= irf_+1 complete */                  \
    TRANSROW(irf_ + 1);                                                       \
    __syncwarp();                                                             \
    ROWLOAD(irf_ + 1);                                                        \
} while (0)

// Guarded tail phase (rows 176..nrows-1).
#define PHASET(P, IRV) do {                                                   \
    const int irt_ = (IRV);                                                   \
    if (irt_ < nrows) {                                                       \
        ROWMATH(P, irt_);                                                     \
        if (irt_ + 3 < nrows) FILLF(irt_ + 3);                                \
        CPA_COMMIT();                                                         \
        CPA_WAIT2();                                                          \
        if (irt_ + 1 < nrows) {                                               \
            TRANSROW(irt_ + 1);                                               \
            __syncwarp();                                                     \
            ROWLOAD(irt_ + 1);                                                \
        }                                                                     \
    }                                                                         \
} while (0)

__global__ void __launch_bounds__(NT, 1)
ssim_main(const float* __restrict__ img1, const float* __restrict__ img2,
          float* __restrict__ out)
{
    // Normalized 1D Gaussian, sigma=1.5, 11 taps
    const float W[11] = {
        0.00102838f, 0.00759874f, 0.03600077f, 0.10936069f, 0.21300553f,
        0.26601180f,
        0.21300553f, 0.10936069f, 0.03600077f, 0.00759874f, 0.00102838f
    };
    // Duplicated 64-bit weight pairs (w|w) for f32x2 ops
    ull W2[11];
#pragma unroll
    for (int k = 0; k < 11; ++k) {
        const unsigned u = __float_as_uint(W[k]);
        W2[k] = ((ull)u << 32) | (ull)u;
    }

    const int band  = blockIdx.x;           // 0..2
    const int plane = blockIdx.y;           // 0..47
    const int t     = threadIdx.x;          // column 0..511
    const int l     = t & 31;               // lane
    const int w     = t >> 5;               // warp
    const int r0    = band * TH;
    const int rows  = (IMH - r0 < TH) ? (IMH - r0) : TH;   // 171/171/170
    const int nrows = rows + 10;            // 181/181/180
    const int pbase = plane * (IMW * IMH);

    // Warp-private 8-deep rotating halo segments.
    // Filled as (img1, img2) by cp.async; transformed in place to (S, D).
    __shared__ float2 seg[8][16][44];

    // Static ring (packed): slot s <-> output rows m with m % 11 == s.
    ull APQ[11], ASD[11];
#pragma unroll
    for (int j = 0; j < 11; ++j) { APQ[j] = 0ULL; ASD[j] = 0ULL; }

    // Prefetched taps of the current row (loaded at end of previous phase).
    ull tp[11];

    // Column mapping:
    //   slot j = l      <-> col t - 5   (valid iff t >= 5)
    //   slot j = 32 + l <-> col t + 27  (exists iff l < 10, valid iff < 512)
    const bool mainok = (t >= 5);
    const bool tailst = (l < 10);
    const bool tailok = tailst && (t + 27 < IMW);

    // Base pointers for this lane's main column (col t-5), row gr=0.
    const float* bp1 = img1 + pbase + (t - 5);
    const float* bp2 = img2 + pbase + (t - 5);

    // u32 shared address of this warp+lane's slot in buffer 0
    unsigned sbu;
    asm("{ .reg .u64 tt; cvta.to.shared.u64 tt, %1; cvt.u32.u64 %0, tt; }"
        : "=r"(sbu) : "l"(&seg[0][w][l]));
    const unsigned BSTRIDE = 16u * 44u * 8u;   // bytes per buffer (5632)

    auto FILLF = [&](int rn) {
        const int gr = r0 - 5 + rn;             // global row (zero pad if OOB)
        const unsigned d = sbu + (unsigned)(rn & 7) * BSTRIDE;
        if ((unsigned)gr < (unsigned)IMH) {
            const float* p1 = bp1 + gr * IMW;   // one IMAD.WIDE each
            const float* p2 = bp2 + gr * IMW;
            if (mainok) { CPA4(d, p1);       CPA4(d + 4u, p2); }
            if (tailok) { CPA4T(d, p1);      CPA4T(d + 4u, p2); }
        } else {
            const float z = 0.f;
            asm volatile("st.shared.v2.f32 [%0], {%1,%1};" :: "r"(d), "f"(z));
            if (tailst)
                asm volatile("st.shared.v2.f32 [%0+256], {%1,%1};"
                             :: "r"(d), "f"(z));
        }
    };

    // Pre-zero slots never written by cp.async (col-invalid); all 8 buffers.
#pragma unroll
    for (int b = 0; b < 8; ++b) {
        if (!mainok)           seg[b][w][l]      = make_float2(0.f, 0.f);
        if (tailst && !tailok) seg[b][w][32 + l] = make_float2(0.f, 0.f);
    }

    // Prologue: rows 0,1,2 in flight; rows 0,1 complete; row 0 transformed
    // and its taps prefetched.
    FILLF(0); CPA_COMMIT();
    FILLF(1); CPA_COMMIT();
    FILLF(2); CPA_COMMIT();
    CPA_WAIT1();                 // rows 0,1 done
    TRANSROW(0);
    __syncwarp();
    ROWLOAD(0);

    float ssum = 0.f;

    // 16 guard-free blocks: rows 0..175 (fill reaches 178 <= nrows-2;
    // TRANS/ROWLOAD reach 176 <= nrows-1 for nrows in {180,181}).
#pragma unroll 1
    for (int base = 0; base < 176; base += 11) {
#pragma unroll
        for (int q = 0; q < 11; ++q) {
            PHASEF(q, base + q);
        }
    }
    // Guarded tail: rows 176..nrows-1 (176 % 11 == 0 -> P == q).
    {
#pragma unroll
        for (int q = 0; q < 11; ++q) {
            PHASET(q, 176 + q);
        }
    }

    // ---- deterministic block reduction ----
    __syncthreads();
#pragma unroll
    for (int off = 16; off; off >>= 1)
        ssum += __shfl_xor_sync(0xffffffffu, ssum, off);

    __shared__ float wsum[16];
    __shared__ bool  islast;
    if (l == 0) wsum[w] = ssum;
    __syncthreads();
    if (t == 0) {
        float v = 0.f;
#pragma unroll
        for (int i = 0; i < 16; ++i) v += wsum[i];
        g_partials[plane * NBANDS + band] = v;
        __threadfence();
        const unsigned n = atomicAdd(&g_count, 1u);
        islast = (n == (unsigned)(NBLOCKS - 1));
    }
    __syncthreads();

    // ---- last CTA: fixed-order (deterministic) final reduction ----
    if (islast) {
        __threadfence();
        float v = (t < NBLOCKS) ? g_partials[t] : 0.f;
#pragma unroll
        for (int off = 16; off; off >>= 1)
            v += __shfl_xor_sync(0xffffffffu, v, off);
        if (l == 0) wsum[w] = v;
        __syncthreads();
        if (t == 0) {
            float s = 0.f;
#pragma unroll
            for (int i = 0; i < 16; ++i) s += wsum[i];
            out[0] = s * (1.0f / 12582912.0f);  // / (16*3*512*512)
            g_count = 0u;                        // reset for next graph replay
        }
    }
}

extern "C" void kernel_launch(void* const* d_in, const int* in_sizes, int n_in,
                              void* d_out, int out_size)
{
    const float* img1 = (const float*)d_in[0];
    const float* img2 = (const float*)d_in[1];
    (void)in_sizes; (void)n_in; (void)out_size;

    dim3 grid(NBANDS, NPLANES);
    ssim_main<<<grid, NT>>>(img1, img2, (float*)d_out);
}

// round 16
// speedup vs baseline: 1.1784x; 1.0292x over previous
#include <cuda_runtime.h>

// ---------------------------------------------------------------------------
// SSIM (16,3,512,512) fp32, 11x11 Gaussian (sigma=1.5), zero pad, global mean.
// R16 = R11 skeleton + PHASE FUSION (2 rows per phase): one wait_group, one
// TRANS pair, one syncwarp, one fill pair per 2 rows; 22 independent LDS and
// two independent h-conv/ring chains per scheduling region (2x ILP).
// W2 symmetry (W[d]==W[10-d]) cuts weight-pair registers 11->6.
// Everything else identical to the proven R11 kernel.
// ---------------------------------------------------------------------------

#define IMW     512
#define IMH     512
#define NT      512                 // one thread per column
#define TH      171                 // output rows per band (3 bands cover 512)
#define NBANDS  3
#define NPLANES 48                  // 16 * 3
#define NBLOCKS (NPLANES * NBANDS)  // 144 CTAs -> single wave
#define SSIM_C1 0.0001f
#define SSIM_C2 0.0009f

typedef unsigned long long ull;

__device__ float        g_partials[NBLOCKS];
__device__ unsigned int g_count;    // zero-init; reset by last block each run

#define CPA4(daddr, sptr) \
    asm volatile("cp.async.ca.shared.global [%0], [%1], 4;" \
                 :: "r"(daddr), "l"(sptr))
#define CPA4T(daddr, sptr) \
    asm volatile("cp.async.ca.shared.global [%0+256], [%1+128], 4;" \
                 :: "r"(daddr), "l"(sptr))
#define CPA_COMMIT() asm volatile("cp.async.commit_group;" ::: "memory")
#define CPA_WAIT2()  asm volatile("cp.async.wait_group 2;"  ::: "memory")
#define CPA_WAIT0()  asm volatile("cp.async.wait_group 0;"  ::: "memory")

#define LDS64(d, a) \
    asm volatile("ld.shared.b64 %0, [%1];" : "=l"(d) : "r"(a))
#define ADD2(d, a, b) \
    asm("add.rn.f32x2 %0, %1, %2;" : "=l"(d) : "l"(a), "l"(b))
#define MUL2(d, a, b) \
    asm("mul.rn.f32x2 %0, %1, %2;" : "=l"(d) : "l"(a), "l"(b))
#define FMA2ACC(acc, a, b) \
    asm("fma.rn.f32x2 %0, %1, %2, %0;" : "+l"(acc) : "l"(a), "l"(b))
#define UNPACK2(lo, hi, s) \
    asm("mov.b64 {%0, %1}, %2;" : "=f"(lo), "=f"(hi) : "l"(s))

// Symmetric weight-pair index: W[d] == W[10-d], only 6 registers needed.
#define WIDX(d) ((d) <= 5 ? (d) : 10 - (d))

// (x,y) -> (x+y, x-y) in place at shared address A (one 8-byte slot)
#define TRANS(A) do {                                                         \
    float xa_, xb_;                                                           \
    asm volatile("ld.shared.v2.f32 {%0,%1}, [%2];"                            \
                 : "=f"(xa_), "=f"(xb_) : "r"(A));                            \
    const float s_ = xa_ + xb_, d_ = xa_ - xb_;                               \
    asm volatile("st.shared.v2.f32 [%0], {%1,%2};"                            \
                 :: "r"(A), "f"(s_), "f"(d_));                                \
} while (0)
#define TRANSROW(rn) do {                                                     \
    const unsigned ta_ = sbu + (unsigned)((rn) & 7) * BSTRIDE;                \
    TRANS(ta_);                                                               \
    if (tailst) TRANS(ta_ + 256u);                                            \
} while (0)

// Load the 11 taps of row rn (already transformed) into array TP.
#define ROWLOADT(rn, TP) do {                                                 \
    const unsigned rl_ = sbu + (unsigned)((rn) & 7) * BSTRIDE;                \
    _Pragma("unroll")                                                         \
    for (int k = 0; k < 11; ++k) LDS64((TP)[k], rl_ + 8u * k);                \
} while (0)

// h-conv + ring + extraction for row ir_, taps in TP.
// P must be a compile-time constant == ir_ mod 11.
#define ROWMATH(P, ir_, TP) do {                                              \
    ull hpq, hsd, tc;                                                         \
    MUL2(hpq, (TP)[5], W2[5]);                                                \
    MUL2(tc,  (TP)[5], (TP)[5]);                                              \
    MUL2(hsd, tc, W2[5]);                                                     \
    _Pragma("unroll")                                                         \
    for (int k = 0; k < 5; ++k) {   /* symmetric pairs (k, 10-k) */           \
        ull ab, sq;                                                           \
        ADD2(ab, (TP)[k], (TP)[10 - k]);                                      \
        FMA2ACC(hpq, ab, W2[k]);                                              \
        MUL2(sq, (TP)[k], (TP)[k]);                                           \
        FMA2ACC(sq, (TP)[10 - k], (TP)[10 - k]);                              \
        FMA2ACC(hsd, sq, W2[k]);                                              \
    }                                                                         \
    _Pragma("unroll")                                                         \
    for (int s = 0; s < 11; ++s) {                                            \
        const int d = ((P) - s + 11) % 11;      /* compile-time */            \
        if (s == (P)) {     /* tap d==0: new output starts -> overwrite */    \
            MUL2(APQ[s], hpq, W2[0]);                                         \
            MUL2(ASD[s], hsd, W2[0]);                                         \
        } else {                                                              \
            FMA2ACC(APQ[s], hpq, W2[WIDX(d)]);                                \
            FMA2ACC(ASD[s], hsd, W2[WIDX(d)]);                                \
        }                                                                     \
    }                                                                         \
    const int e_ = ((P) + 1) % 11;              /* compile-time */            \
    if ((ir_) >= 10) {          /* output row m = ir-10 is real */            \
        float p, q, sv, dv;                                                   \
        UNPACK2(p, q, APQ[e_]);                                               \
        UNPACK2(sv, dv, ASD[e_]);                                             \
        const float a2 = p * p;                                               \
        const float b2 = q * q;                                               \
        const float U  = a2 + b2;                                             \
        const float V  = a2 - b2;                                             \
        const float M  = sv + dv;                                             \
        const float N2 = sv - dv;                                             \
        const float t1 = 0.5f * V + SSIM_C1;                                  \
        const float t2 = 0.5f * (N2 - V) + SSIM_C2;                           \
        const float t3 = 0.5f * U + SSIM_C1;                                  \
        const float t4 = 0.5f * (M - U) + SSIM_C2;                            \
        ssum += __fdividef(t1 * t2, t3 * t4);                                 \
    }                                                                         \
} while (0)

// Fused guard-free phase: rows IRA, IRA+1 (IRA <= 174; fills reach <= 179).
// PA, PB compile-time == IRA mod 11, (IRA+1) mod 11.
#define PHASE2F(PA, PB, IRA) do {                                             \
    const int ira_ = (IRA);                                                   \
    CPA_WAIT2();               /* rows <= ira_+1 complete */                  \
    TRANSROW(ira_);                                                           \
    TRANSROW(ira_ + 1);                                                       \
    FILLF(ira_ + 4); CPA_COMMIT();                                            \
    FILLF(ira_ + 5); CPA_COMMIT();                                            \
    __syncwarp();                                                             \
    ull tpA[11], tpB[11];                                                     \
    ROWLOADT(ira_,     tpA);                                                  \
    ROWLOADT(ira_ + 1, tpB);                                                  \
    ROWMATH(PA, ira_,     tpA);                                               \
    ROWMATH(PB, ira_ + 1, tpB);                                               \
} while (0)

// Guarded tail phase (rows 176..nrows-1), exact wait.
#define PHASET(P, IRV) do {                                                   \
    const int irt_ = (IRV);                                                   \
    if (irt_ < nrows) {                                                       \
        if (irt_ + 3 < nrows) FILLF(irt_ + 3);                                \
        CPA_COMMIT();                                                         \
        CPA_WAIT0();                                                          \
        TRANSROW(irt_);                                                       \
        __syncwarp();                                                         \
        ull tpA[11];                                                          \
        ROWLOADT(irt_, tpA);                                                  \
        ROWMATH(P, irt_, tpA);                                                \
    }                                                                         \
} while (0)

__global__ void __launch_bounds__(NT, 1)
ssim_main(const float* __restrict__ img1, const float* __restrict__ img2,
          float* __restrict__ out)
{
    // Normalized 1D Gaussian, sigma=1.5, 11 taps (symmetric)
    const float W[6] = {
        0.00102838f, 0.00759874f, 0.03600077f, 0.10936069f, 0.21300553f,
        0.26601180f
    };
    // Duplicated 64-bit weight pairs (w|w); symmetry => 6 registers.
    ull W2[6];
#pragma unroll
    for (int k = 0; k < 6; ++k) {
        const unsigned u = __float_as_uint(W[k]);
        W2[k] = ((ull)u << 32) | (ull)u;
    }

    const int band  = blockIdx.x;           // 0..2
    const int plane = blockIdx.y;           // 0..47
    const int t     = threadIdx.x;          // column 0..511
    const int l     = t & 31;               // lane
    const int w     = t >> 5;               // warp
    const int r0    = band * TH;
    const int rows  = (IMH - r0 < TH) ? (IMH - r0) : TH;   // 171/171/170
    const int nrows = rows + 10;            // 181/181/180
    const int pbase = plane * (IMW * IMH);

    // Warp-private 8-deep rotating halo segments.
    // Filled as (img1, img2) by cp.async; transformed in place to (S, D).
    __shared__ float2 seg[8][16][44];

    // Static ring (packed): slot s <-> output rows m with m % 11 == s.
    ull APQ[11], ASD[11];
#pragma unroll
    for (int j = 0; j < 11; ++j) { APQ[j] = 0ULL; ASD[j] = 0ULL; }

    // Column mapping:
    //   slot j = l      <-> col t - 5   (valid iff t >= 5)
    //   slot j = 32 + l <-> col t + 27  (exists iff l < 10, valid iff < 512)
    const bool mainok = (t >= 5);
    const bool tailst = (l < 10);
    const bool tailok = tailst && (t + 27 < IMW);

    // Base pointers for this lane's main column (col t-5), row gr=0.
    const float* bp1 = img1 + pbase + (t - 5);
    const float* bp2 = img2 + pbase + (t - 5);

    // u32 shared address of this warp+lane's slot in buffer 0
    unsigned sbu;
    asm("{ .reg .u64 tt; cvta.to.shared.u64 tt, %1; cvt.u32.u64 %0, tt; }"
        : "=r"(sbu) : "l"(&seg[0][w][l]));
    const unsigned BSTRIDE = 16u * 44u * 8u;   // bytes per buffer (5632)

    auto FILLF = [&](int rn) {
        const int gr = r0 - 5 + rn;             // global row (zero pad if OOB)
        const unsigned d = sbu + (unsigned)(rn & 7) * BSTRIDE;
        if ((unsigned)gr < (unsigned)IMH) {
            const float* p1 = bp1 + gr * IMW;   // one IMAD.WIDE each
            const float* p2 = bp2 + gr * IMW;
            if (mainok) { CPA4(d, p1);       CPA4(d + 4u, p2); }
            if (tailok) { CPA4T(d, p1);      CPA4T(d + 4u, p2); }
        } else {
            const float z = 0.f;
            asm volatile("st.shared.v2.f32 [%0], {%1,%1};" :: "r"(d), "f"(z));
            if (tailst)
                asm volatile("st.shared.v2.f32 [%0+256], {%1,%1};"
                             :: "r"(d), "f"(z));
        }
    };

    // Pre-zero slots never written by cp.async (col-invalid); all 8 buffers.
#pragma unroll
    for (int b = 0; b < 8; ++b) {
        if (!mainok)           seg[b][w][l]      = make_float2(0.f, 0.f);
        if (tailst && !tailok) seg[b][w][32 + l] = make_float2(0.f, 0.f);
    }

    // Prologue: rows 0..3 in flight as four groups.
    FILLF(0); CPA_COMMIT();
    FILLF(1); CPA_COMMIT();
    FILLF(2); CPA_COMMIT();
    FILLF(3); CPA_COMMIT();

    float ssum = 0.f;

    // 8 blocks of 11 fused phases: rows 0..175 (fills reach row 179).
    // base % 22 == 0, so (base + 2i) % 11 and (base + 2i + 1) % 11 are
    // compile-time for i in [0,11).
#pragma unroll 1
    for (int base = 0; base < 176; base += 22) {
#pragma unroll
        for (int i = 0; i < 11; ++i) {
            PHASE2F((2 * i) % 11, (2 * i + 1) % 11, base + 2 * i);
        }
    }
    // Guarded tail: rows 176..nrows-1 (176 % 11 == 0 -> P == q).
    {
#pragma unroll
        for (int q = 0; q < 5; ++q) {
            PHASET(q, 176 + q);
        }
    }

    // ---- deterministic block reduction ----
    __syncthreads();
#pragma unroll
    for (int off = 16; off; off >>= 1)
        ssum += __shfl_xor_sync(0xffffffffu, ssum, off);

    __shared__ float wsum[16];
    __shared__ bool  islast;
    if (l == 0) wsum[w] = ssum;
    __syncthreads();
    if (t == 0) {
        float v = 0.f;
#pragma unroll
        for (int i = 0; i < 16; ++i) v += wsum[i];
        g_partials[plane * NBANDS + band] = v;
        __threadfence();
        const unsigned n = atomicAdd(&g_count, 1u);
        islast = (n == (unsigned)(NBLOCKS - 1));
    }
    __syncthreads();

    // ---- last CTA: fixed-order (deterministic) final reduction ----
    if (islast) {
        __threadfence();
        float v = (t < NBLOCKS) ? g_partials[t] : 0.f;
#pragma unroll
        for (int off = 16; off; off >>= 1)
            v += __shfl_xor_sync(0xffffffffu, v, off);
        if (l == 0) wsum[w] = v;
        __syncthreads();
        if (t == 0) {
            float s = 0.f;
#pragma unroll
            for (int i = 0; i < 16; ++i) s += wsum[i];
            out[0] = s * (1.0f / 12582912.0f);  // / (16*3*512*512)
            g_count = 0u;                        // reset for next graph replay
        }
    }
}

extern "C" void kernel_launch(void* const* d_in, const int* in_sizes, int n_in,
                              void* d_out, int out_size)
{
    const float* img1 = (const float*)d_in[0];
    const float* img2 = (const float*)d_in[1];
    (void)in_sizes; (void)n_in; (void)out_size;

    dim3 grid(NBANDS, NPLANES);
    ssim_main<<<grid, NT>>>(img1, img2, (float*)d_out);
}